// round 15
// baseline (speedup 1.0000x reference)
#include <cuda_runtime.h>
#include <cuda_bf16.h>
#include <math.h>
#include <stdint.h>

#define B_    4096
#define T_    50
#define I_    17
#define H_    256
#define P_    20
#define M_    32
#define NCTA_ 128
#define NTHR_ 512

#define KT0_  18      // GEMM0 k-tiles: 16 (h0) + 2 (x, padded)
#define KT1_  32      // GEMM1 k-tiles: 16 (h0) + 16 (h1)
#define SH0_  296     // b0 row stride (bf16): k 0..255 = h0, 256..287 = x, rest 0
#define SH1_  264     // b1 row stride (bf16)
#define CS_   17      // per-thread c-state stride (floats)

#define DT_   0.1f
#define IMGW_ 1920.0f
#define IMGH_ 1080.0f
#define DIAG_ 2202.9071700822507f

// k-permutation within each 16-chunk of B storage so one thread's four B
// halves (orig k2,k2+1,k2+8,k2+9) are contiguous -> LDS.64.
__device__ __forceinline__ int kperm(int r) {
    return (((r & 7) >> 1) << 2) + (r & 1) + ((r >> 3) << 1);
}

// A-fragment streams, layout [warp16][kt][mt4][lane32] of uint4 (hi bf16 only).
// M-permutation: warp w, m-tile mt=g covers logical rows 256*g + 16*w + r.
__device__ uint4 g_A0[16 * KT0_ * 4 * 32];   // 576 KB
__device__ uint4 g_A1[16 * KT1_ * 4 * 32];   // 1 MB

// ----------------------------- prep: pack fragments --------------------------
__device__ __forceinline__ unsigned short bfhi(float v) {
    return __bfloat16_as_ushort(__float2bfloat16(v));
}
__device__ __forceinline__ unsigned int packw(float a, float b) {
    return (unsigned int)bfhi(a) | ((unsigned int)bfhi(b) << 16);
}
__device__ __forceinline__ float W0at(const float* whh0, const float* wih0,
                                      int row, int k) {
    if (k < 256) return whh0[row * 256 + k];
    int kk = k - 256;
    return kk < I_ ? wih0[row * I_ + kk] : 0.f;
}
__device__ __forceinline__ float W1at(const float* wih1, const float* whh1,
                                      int row, int k) {
    return k < 256 ? wih1[row * 256 + k] : whh1[row * 256 + (k - 256)];
}

__global__ void prep_kernel(const float* __restrict__ whh0,
                            const float* __restrict__ wih0,
                            const float* __restrict__ wih1,
                            const float* __restrict__ whh1)
{
    int idx = blockIdx.x * blockDim.x + threadIdx.x;
    const int N0 = 16 * KT0_ * 128;            // 36864
    const int N1 = 16 * KT1_ * 128;            // 65536
    if (idx < N0) {
        int w  = idx / (KT0_ * 128);
        int r1 = idx % (KT0_ * 128);
        int kt = r1 >> 7;
        int r2 = r1 & 127;
        int mt = r2 >> 5, lane = r2 & 31;
        int R = 256 * mt + 16 * w + (lane >> 2);
        int C = 16 * kt + ((lane & 3) << 1);
        uint4 f;
        f.x = packw(W0at(whh0, wih0, R,     C),     W0at(whh0, wih0, R,     C + 1));
        f.y = packw(W0at(whh0, wih0, R + 8, C),     W0at(whh0, wih0, R + 8, C + 1));
        f.z = packw(W0at(whh0, wih0, R,     C + 8), W0at(whh0, wih0, R,     C + 9));
        f.w = packw(W0at(whh0, wih0, R + 8, C + 8), W0at(whh0, wih0, R + 8, C + 9));
        g_A0[idx] = f;
    } else if (idx < N0 + N1) {
        int id = idx - N0;
        int w  = id / (KT1_ * 128);
        int r1 = id % (KT1_ * 128);
        int kt = r1 >> 7;
        int r2 = r1 & 127;
        int mt = r2 >> 5, lane = r2 & 31;
        int R = 256 * mt + 16 * w + (lane >> 2);
        int C = 16 * kt + ((lane & 3) << 1);
        uint4 f;
        f.x = packw(W1at(wih1, whh1, R,     C),     W1at(wih1, whh1, R,     C + 1));
        f.y = packw(W1at(wih1, whh1, R + 8, C),     W1at(wih1, whh1, R + 8, C + 1));
        f.z = packw(W1at(wih1, whh1, R,     C + 8), W1at(wih1, whh1, R,     C + 9));
        f.w = packw(W1at(wih1, whh1, R + 8, C + 8), W1at(wih1, whh1, R + 8, C + 9));
        g_A1[id] = f;
    }
}

// ------------------------------ main kernel ----------------------------------
struct Smem {
    __nv_bfloat16 b0h[2][M_][SH0_];     // h0 + x, double buffered (k-permuted)
    __nv_bfloat16 b1h[2][M_][SH1_];     // h1 double buffered (k-permuted)
    float c0s[NTHR_ * CS_];
    float c1s[NTHR_ * CS_];
    float biasS[2][4][H_];
    float raw[M_][2 * P_];
};

// hardware tanh (sm_75+): 1 MUFU op, ~2^-11 accuracy
__device__ __forceinline__ float tanh_hw(float x) {
    float t;
    asm("tanh.approx.f32 %0, %1;" : "=f"(t) : "f"(x));
    return t;
}
__device__ __forceinline__ float sigf(float x) {
    // sigmoid(x) = 0.5*tanh(x/2) + 0.5  -> 1 MUFU + 2 FMA
    return fmaf(0.5f, tanh_hw(0.5f * x), 0.5f);
}

__device__ __forceinline__ void mma16816(float d[4],
    unsigned a0, unsigned a1, unsigned a2, unsigned a3,
    unsigned b0, unsigned b1)
{
    asm volatile(
        "mma.sync.aligned.m16n8k16.row.col.f32.bf16.bf16.f32 "
        "{%0,%1,%2,%3},{%4,%5,%6,%7},{%8,%9},{%0,%1,%2,%3};\n"
        : "+f"(d[0]), "+f"(d[1]), "+f"(d[2]), "+f"(d[3])
        : "r"(a0), "r"(a1), "r"(a2), "r"(a3), "r"(b0), "r"(b1));
}

// One GEMM part over KT k-tiles: single bf16 mma per (mt,nt).
// Software pipeline: the full next k-tile's 4 A fragments (16 regs) are
// loaded before the current k-tile's 16-mma block -> ~1 kt of L2-latency cover.
template<int KT>
__device__ __forceinline__ void gemm_part(float (&d)[4][4][4],
    const uint4* __restrict__ pa,
    const __nv_bfloat16* __restrict__ bh,
    const int st, int lane)
{
    const int n8   = lane >> 2;
    const int koff = (lane & 3) << 2;            // permuted: 4*(lane&3)
    uint4 a[4], an[4];
#pragma unroll
    for (int mt = 0; mt < 4; ++mt) a[mt] = pa[mt * 32];
#pragma unroll 1
    for (int kt = 0; kt < KT; ++kt) {
        // issue next k-tile's A loads first (latency cover)
        int nk = (kt + 1 < KT) ? (kt + 1) : kt;
#pragma unroll
        for (int mt = 0; mt < 4; ++mt) an[mt] = pa[(nk * 4 + mt) * 32];
        // B loads for this k-tile
        uint2 bh2[4];
#pragma unroll
        for (int nt = 0; nt < 4; ++nt) {
            int off = (8 * nt + n8) * st + 16 * kt + koff;
            bh2[nt] = *(const uint2*)(bh + off);
        }
#pragma unroll
        for (int mt = 0; mt < 4; ++mt)
#pragma unroll
            for (int nt = 0; nt < 4; ++nt)
                mma16816(d[mt][nt], a[mt].x, a[mt].y, a[mt].z, a[mt].w,
                         bh2[nt].x, bh2[nt].y);
#pragma unroll
        for (int mt = 0; mt < 4; ++mt) a[mt] = an[mt];
    }
}

__device__ __forceinline__ void zero_d(float (&d)[4][4][4]) {
#pragma unroll
    for (int mt = 0; mt < 4; ++mt)
#pragma unroll
        for (int nt = 0; nt < 4; ++nt)
#pragma unroll
            for (int q = 0; q < 4; ++q) d[mt][nt][q] = 0.f;
}

// In-register LSTM cell update; h written at k-permuted column positions.
__device__ __forceinline__ void epilogue(const float (&d)[4][4][4],
    float* __restrict__ cS, const float* __restrict__ biasL,
    __nv_bfloat16* __restrict__ bh, int st,
    int warp, int lane)
{
    const int jr = lane >> 2;
    const int k2 = (lane & 3) << 1;
    const int ja = 16 * warp + jr;
    const int jp = 16 * warp + ((jr >> 1) << 2) + (jr & 1);
    float bi[4][2];
#pragma unroll
    for (int g = 0; g < 4; ++g) {
        bi[g][0] = biasL[g * H_ + ja];
        bi[g][1] = biasL[g * H_ + ja + 8];
    }
#pragma unroll
    for (int nt = 0; nt < 4; ++nt) {
#pragma unroll
        for (int q = 0; q < 4; ++q) {
            int jh = q >> 1;
            int jcol = jp + 2 * jh;                 // permuted storage column
            int n  = 8 * nt + k2 + (q & 1);
            int ci = nt * 4 + q;
            float pi = d[0][nt][q] + bi[0][jh];
            float pf = d[1][nt][q] + bi[1][jh];
            float pg = d[2][nt][q] + bi[2][jh];
            float po = d[3][nt][q] + bi[3][jh];
            float c  = sigf(pf) * cS[ci] + sigf(pi) * tanh_hw(pg);
            cS[ci]   = c;
            float h  = sigf(po) * tanh_hw(c);
            bh[n * st + jcol] = __float2bfloat16(h);
        }
    }
}

__global__ void __launch_bounds__(NTHR_, 1)
lstm_kin_kernel(const float* __restrict__ x,
                const float* __restrict__ bih0, const float* __restrict__ bhh0,
                const float* __restrict__ bih1, const float* __restrict__ bhh1,
                const float* __restrict__ fcw,  const float* __restrict__ fcb,
                float* __restrict__ out)
{
    extern __shared__ char smem_raw[];
    Smem* S = reinterpret_cast<Smem*>(smem_raw);

    const int tid  = threadIdx.x;
    const int warp = tid >> 5;
    const int lane = tid & 31;
    const int row0 = blockIdx.x * M_;

    const uint4* __restrict__ pa0 = g_A0 + (size_t)warp * KT0_ * 128 + lane;
    const uint4* __restrict__ pa1 = g_A1 + (size_t)warp * KT1_ * 128 + lane;

    // zero B buffers + c-state
    {
        unsigned* z = (unsigned*)S->b0h;
        const int nb0 = 2 * M_ * SH0_ / 2;
        for (int i = tid; i < nb0; i += NTHR_) z[i] = 0u;
        unsigned* z1 = (unsigned*)S->b1h;
        const int nb1 = 2 * M_ * SH1_ / 2;
        for (int i = tid; i < nb1; i += NTHR_) z1[i] = 0u;
    }
    for (int i = tid; i < NTHR_ * CS_; i += NTHR_) { S->c0s[i] = 0.f; S->c1s[i] = 0.f; }
    for (int i = tid; i < 4 * H_; i += NTHR_) {
        ((float*)S->biasS[0])[i] = bih0[i] + bhh0[i];
        ((float*)S->biasS[1])[i] = bih1[i] + bhh1[i];
    }
    // x(t=0) into b0[0] x-section, k-permuted within its 16-chunks
    for (int idx = tid; idx < M_ * I_; idx += NTHR_) {
        int n = idx / I_, kk = idx % I_;
        int pos = 256 + (kk & ~15) + kperm(kk & 15);
        float v = x[((size_t)(row0 + n) * T_ + 0) * I_ + kk];
        S->b0h[0][n][pos] = __float2bfloat16(v);
    }
    __syncthreads();

    float* cS0 = &S->c0s[tid * CS_];
    float* cS1 = &S->c1s[tid * CS_];

    int pb0 = 0, pb1 = 0;
    float d[4][4][4];

#pragma unroll 1
    for (int t = 0; t < T_; ++t) {
        // ---- GEMM0: gates0(t) = whh0*h0(t-1) + wih0*x(t) ----
        zero_d(d);
        gemm_part<16>(d, pa0, &S->b0h[pb0][0][0], SH0_, lane);
        gemm_part<2>(d, pa0 + 16 * 128, &S->b0h[pb0][0][0] + 256, SH0_, lane);
        epilogue(d, cS0, &S->biasS[0][0][0],
                 &S->b0h[pb0 ^ 1][0][0], SH0_, warp, lane);
        // prefetch x(t+1) into b0[pb0^1] x-section
        if (t + 1 < T_) {
            for (int idx = tid; idx < M_ * I_; idx += NTHR_) {
                int n = idx / I_, kk = idx % I_;
                int pos = 256 + (kk & ~15) + kperm(kk & 15);
                float v = x[((size_t)(row0 + n) * T_ + (t + 1)) * I_ + kk];
                S->b0h[pb0 ^ 1][n][pos] = __float2bfloat16(v);
            }
        }
        __syncthreads();   // single barrier per step

        // ---- GEMM1: gates1(t) = wih1*h0(t) + whh1*h1(t-1) ----
        zero_d(d);
        gemm_part<16>(d, pa1, &S->b0h[pb0 ^ 1][0][0], SH0_, lane);
        gemm_part<16>(d, pa1 + 16 * 128, &S->b1h[pb1][0][0], SH1_, lane);
        epilogue(d, cS1, &S->biasS[1][0][0],
                 &S->b1h[pb1 ^ 1][0][0], SH1_, warp, lane);

        pb0 ^= 1; pb1 ^= 1;
    }
    __syncthreads();

    // ================= FC head (undo k-permutation when reading h1) ==========
    for (int idx = tid; idx < M_ * 2 * P_; idx += NTHR_) {
        int m = idx / (2 * P_), q = idx % (2 * P_);
        const float* wq = fcw + (size_t)q * H_;
        float s = fcb[q];
#pragma unroll 4
        for (int k = 0; k < H_; ++k) {
            int ks = (k & ~15) + kperm(k & 15);
            s += wq[k] * __bfloat162float(S->b1h[pb1][m][ks]);
        }
        S->raw[m][q] = s;
    }
    __syncthreads();

    // ================= kinematic rollout =================
    if (tid < M_) {
        const int m   = tid;
        const int row = row0 + m;
        const float* xl = x + ((size_t)row * T_ + (T_ - 1)) * I_;
        float psi = atan2f(xl[7], xl[8]);
        float X   = xl[0] * IMGW_;
        float Y   = xl[1] * IMGH_;
        float decay = 1.f;
        float* o = out + (size_t)row * P_ * 2;
#pragma unroll 1
        for (int p = 0; p < P_; ++p) {
            float sraw = S->raw[m][2 * p];
            float yaw  = S->raw[m][2 * p + 1];
            float speed = fmaxf(sraw, 0.f) + log1pf(expf(-fabsf(sraw)));
            float w = yaw * decay;
            decay *= 0.97f;
            float v = speed * DIAG_;
            float psi_prev  = psi;
            float psi_after = psi + w * DT_;
            psi = psi_after;
            float is_s  = (fabsf(w) < 0.01f) ? 1.f : 0.f;
            float wsafe = w + is_s * 0.0001f;
            float radius = v / wsafe;
            float sp = sinf(psi_prev),  cp = cosf(psi_prev);
            float sa = sinf(psi_after), ca = cosf(psi_after);
            float dxs = v * cp * DT_;
            float dys = v * sp * DT_;
            float dxt = radius * (sa - sp);
            float dyt = -radius * (ca - cp);
            float dx = is_s * dxs + (1.f - is_s) * dxt;
            float dy = is_s * dys + (1.f - is_s) * dyt;
            X += dx;
            Y += dy;
            o[2 * p]     = X / IMGW_;
            o[2 * p + 1] = Y / IMGH_;
        }
    }
}

extern "C" void kernel_launch(void* const* d_in, const int* in_sizes, int n_in,
                              void* d_out, int out_size)
{
    (void)in_sizes; (void)n_in; (void)out_size;
    const float* x    = (const float*)d_in[0];
    const float* wih0 = (const float*)d_in[1];
    const float* whh0 = (const float*)d_in[2];
    const float* bih0 = (const float*)d_in[3];
    const float* bhh0 = (const float*)d_in[4];
    const float* wih1 = (const float*)d_in[5];
    const float* whh1 = (const float*)d_in[6];
    const float* bih1 = (const float*)d_in[7];
    const float* bhh1 = (const float*)d_in[8];
    const float* fcw  = (const float*)d_in[9];
    const float* fcb  = (const float*)d_in[10];
    float* out = (float*)d_out;

    const int nprep = 16 * KT0_ * 128 + 16 * KT1_ * 128;
    prep_kernel<<<(nprep + 255) / 256, 256>>>(whh0, wih0, wih1, whh1);

    cudaFuncSetAttribute(lstm_kin_kernel,
                         cudaFuncAttributeMaxDynamicSharedMemorySize,
                         (int)sizeof(Smem));

    lstm_kin_kernel<<<NCTA_, NTHR_, sizeof(Smem)>>>(
        x, bih0, bhh0, bih1, bhh1, fcw, fcb, out);
}

// round 16
// speedup vs baseline: 1.1694x; 1.1694x over previous
#include <cuda_runtime.h>
#include <cuda_bf16.h>
#include <math.h>
#include <stdint.h>

#define B_    4096
#define T_    50
#define I_    17
#define H_    256
#define P_    20
#define M_    32
#define NCTA_ 128
#define NTHR_ 512

#define KT0_  18      // GEMM0 k-tiles: 16 (h0) + 2 (x, padded)
#define KT1_  32      // GEMM1 k-tiles: 16 (h0) + 16 (h1)
#define SH0_  296     // b0 row stride (bf16): k 0..255 = h0, 256..287 = x, rest 0
#define SH1_  264     // b1 row stride (bf16)
#define CS_   17      // per-thread c-state stride (floats)

#define DT_   0.1f
#define IMGW_ 1920.0f
#define IMGH_ 1080.0f
#define DIAG_ 2202.9071700822507f

// k-permutation within each 16-chunk of B storage so one thread's four B
// halves (orig k2,k2+1,k2+8,k2+9) are contiguous -> LDS.64.
__device__ __forceinline__ int kperm(int r) {
    return (((r & 7) >> 1) << 2) + (r & 1) + ((r >> 3) << 1);
}

// A-fragment streams, layout [warp16][kt][mt4][lane32] of uint4 (hi bf16 only).
// M-permutation: warp w, m-tile mt=g covers logical rows 256*g + 16*w + r.
__device__ uint4 g_A0[16 * KT0_ * 4 * 32];   // 576 KB
__device__ uint4 g_A1[16 * KT1_ * 4 * 32];   // 1 MB

// ----------------------------- prep: pack fragments --------------------------
__device__ __forceinline__ unsigned short bfhi(float v) {
    return __bfloat16_as_ushort(__float2bfloat16(v));
}
__device__ __forceinline__ unsigned int packw(float a, float b) {
    return (unsigned int)bfhi(a) | ((unsigned int)bfhi(b) << 16);
}
__device__ __forceinline__ float W0at(const float* whh0, const float* wih0,
                                      int row, int k) {
    if (k < 256) return whh0[row * 256 + k];
    int kk = k - 256;
    return kk < I_ ? wih0[row * I_ + kk] : 0.f;
}
__device__ __forceinline__ float W1at(const float* wih1, const float* whh1,
                                      int row, int k) {
    return k < 256 ? wih1[row * 256 + k] : whh1[row * 256 + (k - 256)];
}

__global__ void prep_kernel(const float* __restrict__ whh0,
                            const float* __restrict__ wih0,
                            const float* __restrict__ wih1,
                            const float* __restrict__ whh1)
{
    int idx = blockIdx.x * blockDim.x + threadIdx.x;
    const int N0 = 16 * KT0_ * 128;            // 36864
    const int N1 = 16 * KT1_ * 128;            // 65536
    if (idx < N0) {
        int w  = idx / (KT0_ * 128);
        int r1 = idx % (KT0_ * 128);
        int kt = r1 >> 7;
        int r2 = r1 & 127;
        int mt = r2 >> 5, lane = r2 & 31;
        int R = 256 * mt + 16 * w + (lane >> 2);
        int C = 16 * kt + ((lane & 3) << 1);
        uint4 f;
        f.x = packw(W0at(whh0, wih0, R,     C),     W0at(whh0, wih0, R,     C + 1));
        f.y = packw(W0at(whh0, wih0, R + 8, C),     W0at(whh0, wih0, R + 8, C + 1));
        f.z = packw(W0at(whh0, wih0, R,     C + 8), W0at(whh0, wih0, R,     C + 9));
        f.w = packw(W0at(whh0, wih0, R + 8, C + 8), W0at(whh0, wih0, R + 8, C + 9));
        g_A0[idx] = f;
    } else if (idx < N0 + N1) {
        int id = idx - N0;
        int w  = id / (KT1_ * 128);
        int r1 = id % (KT1_ * 128);
        int kt = r1 >> 7;
        int r2 = r1 & 127;
        int mt = r2 >> 5, lane = r2 & 31;
        int R = 256 * mt + 16 * w + (lane >> 2);
        int C = 16 * kt + ((lane & 3) << 1);
        uint4 f;
        f.x = packw(W1at(wih1, whh1, R,     C),     W1at(wih1, whh1, R,     C + 1));
        f.y = packw(W1at(wih1, whh1, R + 8, C),     W1at(wih1, whh1, R + 8, C + 1));
        f.z = packw(W1at(wih1, whh1, R,     C + 8), W1at(wih1, whh1, R,     C + 9));
        f.w = packw(W1at(wih1, whh1, R + 8, C + 8), W1at(wih1, whh1, R + 8, C + 9));
        g_A1[id] = f;
    }
}

// ------------------------------ main kernel ----------------------------------
struct Smem {
    __nv_bfloat16 b0h[2][M_][SH0_];     // h0 + x, double buffered (k-permuted)
    __nv_bfloat16 b1h[2][M_][SH1_];     // h1 double buffered (k-permuted)
    float c0s[NTHR_ * CS_];
    float c1s[NTHR_ * CS_];
    float biasS[2][4][H_];
    float raw[M_][2 * P_];
};

// hardware tanh (sm_75+): 1 MUFU op, ~2^-11 accuracy
__device__ __forceinline__ float tanh_hw(float x) {
    float t;
    asm("tanh.approx.f32 %0, %1;" : "=f"(t) : "f"(x));
    return t;
}
__device__ __forceinline__ float sigf(float x) {
    // sigmoid(x) = 0.5*tanh(x/2) + 0.5  -> 1 MUFU + 2 FMA
    return fmaf(0.5f, tanh_hw(0.5f * x), 0.5f);
}

__device__ __forceinline__ void mma16816(float d[4],
    unsigned a0, unsigned a1, unsigned a2, unsigned a3,
    unsigned b0, unsigned b1)
{
    asm volatile(
        "mma.sync.aligned.m16n8k16.row.col.f32.bf16.bf16.f32 "
        "{%0,%1,%2,%3},{%4,%5,%6,%7},{%8,%9},{%0,%1,%2,%3};\n"
        : "+f"(d[0]), "+f"(d[1]), "+f"(d[2]), "+f"(d[3])
        : "r"(a0), "r"(a1), "r"(a2), "r"(a3), "r"(b0), "r"(b1));
}

// One GEMM part over KT k-tiles: single bf16 mma per (mt,nt).
// R14's single-fragment rotation (the full-kt prefetch of R15 regressed).
template<int KT>
__device__ __forceinline__ void gemm_part(float (&d)[4][4][4],
    const uint4* __restrict__ pa,
    const __nv_bfloat16* __restrict__ bh,
    const int st, int lane)
{
    const int n8   = lane >> 2;
    const int koff = (lane & 3) << 2;            // permuted: 4*(lane&3)
    uint4 a = pa[0];
#pragma unroll 1
    for (int kt = 0; kt < KT; ++kt) {
        uint2 bh2[4];
#pragma unroll
        for (int nt = 0; nt < 4; ++nt) {
            int off = (8 * nt + n8) * st + 16 * kt + koff;
            bh2[nt] = *(const uint2*)(bh + off);
        }
#pragma unroll
        for (int mt = 0; mt < 4; ++mt) {
            int ni = kt * 4 + mt + 1;
            if (ni > KT * 4 - 1) ni = KT * 4 - 1;   // clamp (reload last, unused)
            uint4 an = pa[ni * 32];
#pragma unroll
            for (int nt = 0; nt < 4; ++nt) {
                mma16816(d[mt][nt], a.x, a.y, a.z, a.w, bh2[nt].x, bh2[nt].y);
            }
            a = an;
        }
    }
}

__device__ __forceinline__ void zero_d(float (&d)[4][4][4]) {
#pragma unroll
    for (int mt = 0; mt < 4; ++mt)
#pragma unroll
        for (int nt = 0; nt < 4; ++nt)
#pragma unroll
            for (int q = 0; q < 4; ++q) d[mt][nt][q] = 0.f;
}

// In-register LSTM cell update; h written at k-permuted column positions.
// MUFU-lean activations: 5 MUFU/cell (was 10 with exp-based sigmoid/tanh).
__device__ __forceinline__ void epilogue(const float (&d)[4][4][4],
    float* __restrict__ cS, const float* __restrict__ biasL,
    __nv_bfloat16* __restrict__ bh, int st,
    int warp, int lane)
{
    const int jr = lane >> 2;
    const int k2 = (lane & 3) << 1;
    const int ja = 16 * warp + jr;
    const int jp = 16 * warp + ((jr >> 1) << 2) + (jr & 1);
    float bi[4][2];
#pragma unroll
    for (int g = 0; g < 4; ++g) {
        bi[g][0] = biasL[g * H_ + ja];
        bi[g][1] = biasL[g * H_ + ja + 8];
    }
#pragma unroll
    for (int nt = 0; nt < 4; ++nt) {
#pragma unroll
        for (int q = 0; q < 4; ++q) {
            int jh = q >> 1;
            int jcol = jp + 2 * jh;                 // permuted storage column
            int n  = 8 * nt + k2 + (q & 1);
            int ci = nt * 4 + q;
            float pi = d[0][nt][q] + bi[0][jh];
            float pf = d[1][nt][q] + bi[1][jh];
            float pg = d[2][nt][q] + bi[2][jh];
            float po = d[3][nt][q] + bi[3][jh];
            float c  = sigf(pf) * cS[ci] + sigf(pi) * tanh_hw(pg);
            cS[ci]   = c;
            float h  = sigf(po) * tanh_hw(c);
            bh[n * st + jcol] = __float2bfloat16(h);
        }
    }
}

__global__ void __launch_bounds__(NTHR_, 1)
lstm_kin_kernel(const float* __restrict__ x,
                const float* __restrict__ bih0, const float* __restrict__ bhh0,
                const float* __restrict__ bih1, const float* __restrict__ bhh1,
                const float* __restrict__ fcw,  const float* __restrict__ fcb,
                float* __restrict__ out)
{
    extern __shared__ char smem_raw[];
    Smem* S = reinterpret_cast<Smem*>(smem_raw);

    const int tid  = threadIdx.x;
    const int warp = tid >> 5;
    const int lane = tid & 31;
    const int row0 = blockIdx.x * M_;

    const uint4* __restrict__ pa0 = g_A0 + (size_t)warp * KT0_ * 128 + lane;
    const uint4* __restrict__ pa1 = g_A1 + (size_t)warp * KT1_ * 128 + lane;

    // zero B buffers + c-state
    {
        unsigned* z = (unsigned*)S->b0h;
        const int nb0 = 2 * M_ * SH0_ / 2;
        for (int i = tid; i < nb0; i += NTHR_) z[i] = 0u;
        unsigned* z1 = (unsigned*)S->b1h;
        const int nb1 = 2 * M_ * SH1_ / 2;
        for (int i = tid; i < nb1; i += NTHR_) z1[i] = 0u;
    }
    for (int i = tid; i < NTHR_ * CS_; i += NTHR_) { S->c0s[i] = 0.f; S->c1s[i] = 0.f; }
    for (int i = tid; i < 4 * H_; i += NTHR_) {
        ((float*)S->biasS[0])[i] = bih0[i] + bhh0[i];
        ((float*)S->biasS[1])[i] = bih1[i] + bhh1[i];
    }
    // x(t=0) into b0[0] x-section, k-permuted within its 16-chunks
    for (int idx = tid; idx < M_ * I_; idx += NTHR_) {
        int n = idx / I_, kk = idx % I_;
        int pos = 256 + (kk & ~15) + kperm(kk & 15);
        float v = x[((size_t)(row0 + n) * T_ + 0) * I_ + kk];
        S->b0h[0][n][pos] = __float2bfloat16(v);
    }
    __syncthreads();

    float* cS0 = &S->c0s[tid * CS_];
    float* cS1 = &S->c1s[tid * CS_];

    int pb0 = 0, pb1 = 0;
    float d[4][4][4];

#pragma unroll 1
    for (int t = 0; t < T_; ++t) {
        // ---- GEMM0: gates0(t) = whh0*h0(t-1) + wih0*x(t) ----
        zero_d(d);
        gemm_part<16>(d, pa0, &S->b0h[pb0][0][0], SH0_, lane);
        gemm_part<2>(d, pa0 + 16 * 128, &S->b0h[pb0][0][0] + 256, SH0_, lane);
        epilogue(d, cS0, &S->biasS[0][0][0],
                 &S->b0h[pb0 ^ 1][0][0], SH0_, warp, lane);
        // prefetch x(t+1) into b0[pb0^1] x-section
        if (t + 1 < T_) {
            for (int idx = tid; idx < M_ * I_; idx += NTHR_) {
                int n = idx / I_, kk = idx % I_;
                int pos = 256 + (kk & ~15) + kperm(kk & 15);
                float v = x[((size_t)(row0 + n) * T_ + (t + 1)) * I_ + kk];
                S->b0h[pb0 ^ 1][n][pos] = __float2bfloat16(v);
            }
        }
        __syncthreads();   // single barrier per step

        // ---- GEMM1: gates1(t) = wih1*h0(t) + whh1*h1(t-1) ----
        zero_d(d);
        gemm_part<16>(d, pa1, &S->b0h[pb0 ^ 1][0][0], SH0_, lane);
        gemm_part<16>(d, pa1 + 16 * 128, &S->b1h[pb1][0][0], SH1_, lane);
        epilogue(d, cS1, &S->biasS[1][0][0],
                 &S->b1h[pb1 ^ 1][0][0], SH1_, warp, lane);

        pb0 ^= 1; pb1 ^= 1;
    }
    __syncthreads();

    // ================= FC head (undo k-permutation when reading h1) ==========
    for (int idx = tid; idx < M_ * 2 * P_; idx += NTHR_) {
        int m = idx / (2 * P_), q = idx % (2 * P_);
        const float* wq = fcw + (size_t)q * H_;
        float s = fcb[q];
#pragma unroll 4
        for (int k = 0; k < H_; ++k) {
            int ks = (k & ~15) + kperm(k & 15);
            s += wq[k] * __bfloat162float(S->b1h[pb1][m][ks]);
        }
        S->raw[m][q] = s;
    }
    __syncthreads();

    // ================= kinematic rollout =================
    if (tid < M_) {
        const int m   = tid;
        const int row = row0 + m;
        const float* xl = x + ((size_t)row * T_ + (T_ - 1)) * I_;
        float psi = atan2f(xl[7], xl[8]);
        float X   = xl[0] * IMGW_;
        float Y   = xl[1] * IMGH_;
        float decay = 1.f;
        float* o = out + (size_t)row * P_ * 2;
#pragma unroll 1
        for (int p = 0; p < P_; ++p) {
            float sraw = S->raw[m][2 * p];
            float yaw  = S->raw[m][2 * p + 1];
            float speed = fmaxf(sraw, 0.f) + log1pf(expf(-fabsf(sraw)));
            float w = yaw * decay;
            decay *= 0.97f;
            float v = speed * DIAG_;
            float psi_prev  = psi;
            float psi_after = psi + w * DT_;
            psi = psi_after;
            float is_s  = (fabsf(w) < 0.01f) ? 1.f : 0.f;
            float wsafe = w + is_s * 0.0001f;
            float radius = v / wsafe;
            float sp = sinf(psi_prev),  cp = cosf(psi_prev);
            float sa = sinf(psi_after), ca = cosf(psi_after);
            float dxs = v * cp * DT_;
            float dys = v * sp * DT_;
            float dxt = radius * (sa - sp);
            float dyt = -radius * (ca - cp);
            float dx = is_s * dxs + (1.f - is_s) * dxt;
            float dy = is_s * dys + (1.f - is_s) * dyt;
            X += dx;
            Y += dy;
            o[2 * p]     = X / IMGW_;
            o[2 * p + 1] = Y / IMGH_;
        }
    }
}

extern "C" void kernel_launch(void* const* d_in, const int* in_sizes, int n_in,
                              void* d_out, int out_size)
{
    (void)in_sizes; (void)n_in; (void)out_size;
    const float* x    = (const float*)d_in[0];
    const float* wih0 = (const float*)d_in[1];
    const float* whh0 = (const float*)d_in[2];
    const float* bih0 = (const float*)d_in[3];
    const float* bhh0 = (const float*)d_in[4];
    const float* wih1 = (const float*)d_in[5];
    const float* whh1 = (const float*)d_in[6];
    const float* bih1 = (const float*)d_in[7];
    const float* bhh1 = (const float*)d_in[8];
    const float* fcw  = (const float*)d_in[9];
    const float* fcb  = (const float*)d_in[10];
    float* out = (float*)d_out;

    const int nprep = 16 * KT0_ * 128 + 16 * KT1_ * 128;
    prep_kernel<<<(nprep + 255) / 256, 256>>>(whh0, wih0, wih1, whh1);

    cudaFuncSetAttribute(lstm_kin_kernel,
                         cudaFuncAttributeMaxDynamicSharedMemorySize,
                         (int)sizeof(Smem));

    lstm_kin_kernel<<<NCTA_, NTHR_, sizeof(Smem)>>>(
        x, bih0, bhh0, bih1, bhh1, fcw, fcb, out);
}